// round 2
// baseline (speedup 1.0000x reference)
#include <cuda_runtime.h>
#include <math.h>
#include <stdint.h>

#define NB 64
#define LT 1024
#define HD 512
#define RSTR 516   // padded smem row stride (floats): conflict-free + float4-aligned

// Scratch (static device arrays: allocation-free).
// g_pre [dir][t][n][h]  : x-projection + bias, 256 MB
// g_hist[dir][t][n][h]  : hidden states, t=1..1024 (slot 0 unused), 256 MB
__device__ float g_pre[(size_t)2 * LT * NB * HD];
__device__ float g_hist[(size_t)2 * (LT + 1) * NB * HD];
__device__ unsigned g_bar;       // zero-init; reset at kernel end
__device__ unsigned g_bar_exit;

// ---------------------------------------------------------------------------
// Tiled fp32 GEMM: C[64x64 tile] = A(Mx512) * B(512x512 rows, K-major)^T
// mode 0: xproj  -> writes g_pre with time mapping (bw flips t), bias = b1+b2
// mode 1: fc     -> A = g_hist[dir][1..1024], writes y with dir column offset
// ---------------------------------------------------------------------------
__global__ void __launch_bounds__(256) gemm64(
    const float* __restrict__ Ap, const float* __restrict__ B,
    const float* __restrict__ bias1, const float* __restrict__ bias2,
    float* __restrict__ yout, int mode, int dir)
{
    __shared__ float As[16][68];
    __shared__ float Bs[16][68];

    const float* A = (mode == 0)
        ? Ap
        : (g_hist + (size_t)dir * (LT + 1) * NB * HD + (size_t)NB * HD);

    const int m0 = blockIdx.y * 64;
    const int n0 = blockIdx.x * 64;
    const int tid  = threadIdx.x;
    const int lrow = tid >> 2;          // 0..63
    const int lk   = (tid & 3) << 2;    // 0,4,8,12
    const int tx = tid & 15;
    const int ty = tid >> 4;

    float acc[4][4];
#pragma unroll
    for (int i = 0; i < 4; i++)
#pragma unroll
        for (int j = 0; j < 4; j++) acc[i][j] = 0.f;

    for (int kt = 0; kt < HD; kt += 16) {
        float4 av = *(const float4*)(A + (size_t)(m0 + lrow) * HD + kt + lk);
        float4 bv = *(const float4*)(B + (size_t)(n0 + lrow) * HD + kt + lk);
        As[lk + 0][lrow] = av.x; As[lk + 1][lrow] = av.y;
        As[lk + 2][lrow] = av.z; As[lk + 3][lrow] = av.w;
        Bs[lk + 0][lrow] = bv.x; Bs[lk + 1][lrow] = bv.y;
        Bs[lk + 2][lrow] = bv.z; Bs[lk + 3][lrow] = bv.w;
        __syncthreads();
#pragma unroll
        for (int kk = 0; kk < 16; kk++) {
            float a[4], b[4];
            *(float4*)a = *(const float4*)&As[kk][ty << 2];
            *(float4*)b = *(const float4*)&Bs[kk][tx << 2];
#pragma unroll
            for (int i = 0; i < 4; i++)
#pragma unroll
                for (int j = 0; j < 4; j++) acc[i][j] += a[i] * b[j];
        }
        __syncthreads();
    }

    float bs[4];
#pragma unroll
    for (int j = 0; j < 4; j++) {
        int n = n0 + (tx << 2) + j;
        bs[j] = bias1[n] + (bias2 ? bias2[n] : 0.f);
    }

#pragma unroll
    for (int i = 0; i < 4; i++) {
        int m = m0 + (ty << 2) + i;
#pragma unroll
        for (int j = 0; j < 4; j++) {
            int n = n0 + (tx << 2) + j;
            float v = acc[i][j] + bs[j];
            if (mode == 0) {
                // m = nb*1024 + tt (tt = source time index into x)
                int nb = m >> 10, tt = m & (LT - 1);
                int td = dir ? (LT - 1 - tt) : tt;  // scan step this pre feeds
                g_pre[(((size_t)dir * LT + td) * NB + nb) * HD + n] = v;
            } else {
                // m = t*64 + nb ; y[n][t][dir*512 + h]
                int t = m >> 6, nb = m & (NB - 1);
                yout[((size_t)nb * LT + t) * (2 * HD) + (size_t)dir * HD + n] = v;
            }
        }
    }
}

// ---------------------------------------------------------------------------
// Persistent recurrence kernel: 128 CTAs, grid barrier each step.
// CTA = (dir, 64-wide h block, 8-wide n block); Whh slice resident in SMEM.
// ---------------------------------------------------------------------------
__global__ void __launch_bounds__(128) rnn_kernel(
    const float* __restrict__ h0in,
    const float* __restrict__ Wfw, const float* __restrict__ Wbw)
{
    extern __shared__ float sm[];
    float* Wsh = sm;               // 64 rows x RSTR
    float* hsh = sm + 64 * RSTR;   // 8 rows  x RSTR

    const int b   = blockIdx.x;
    const int dir = b >> 6;
    const int sub = b & 63;
    const int hb  = (sub >> 3) << 6;  // h block base (0..448)
    const int nb  = (sub & 7) << 3;   // n block base (0..56)
    const int tid = threadIdx.x;
    const float* W = dir ? Wbw : Wfw;

    // Load Whh slice [64][512] once (stays resident for all 1024 steps)
    for (int i = tid; i < 64 * 128; i += 128) {
        int r = i >> 7, c4 = (i & 127) << 2;
        *(float4*)&Wsh[r * RSTR + c4] =
            *(const float4*)&W[(size_t)(hb + r) * HD + c4];
    }

    const float* preb  = g_pre  + (size_t)dir * LT * NB * HD;
    float*       histb = g_hist + (size_t)dir * (LT + 1) * NB * HD;

    const int a  = tid & 3;        // n pair selector (4 -> 8 rows)
    const int c  = tid >> 2;       // h pair selector (32 -> 64 cols)
    const int na = nb + (a << 1);
    const int hc = hb + (c << 1);
    const float* hr0 = &hsh[(a << 1) * RSTR];
    const float* hr1 = hr0 + RSTR;
    const float* wr0 = &Wsh[(c << 1) * RSTR];
    const float* wr1 = wr0 + RSTR;

    unsigned target = 0;
    const unsigned G = gridDim.x;
    __syncthreads();

    for (int t = 0; t < LT; t++) {
        // Stage h_{t-1} rows nb..nb+7 (16 KB) into SMEM
        const float* hsrc = (t == 0)
            ? (h0in + ((size_t)dir * NB + nb) * HD)
            : (histb + ((size_t)t * NB + nb) * HD);
        for (int i = tid; i < 8 * 128; i += 128) {
            int r = i >> 7, c4 = (i & 127) << 2;
            *(float4*)&hsh[r * RSTR + c4] =
                *(const float4*)&hsrc[(size_t)r * HD + c4];
        }
        __syncthreads();

        const float* pr = preb + (size_t)t * NB * HD;
        float acc00 = pr[(size_t)na * HD + hc];
        float acc01 = pr[(size_t)na * HD + hc + 1];
        float acc10 = pr[(size_t)(na + 1) * HD + hc];
        float acc11 = pr[(size_t)(na + 1) * HD + hc + 1];

#pragma unroll 8
        for (int k = 0; k < HD; k += 4) {
            float4 h0v = *(const float4*)(hr0 + k);
            float4 h1v = *(const float4*)(hr1 + k);
            float4 w0v = *(const float4*)(wr0 + k);
            float4 w1v = *(const float4*)(wr1 + k);
            acc00 += h0v.x * w0v.x + h0v.y * w0v.y + h0v.z * w0v.z + h0v.w * w0v.w;
            acc01 += h0v.x * w1v.x + h0v.y * w1v.y + h0v.z * w1v.z + h0v.w * w1v.w;
            acc10 += h1v.x * w0v.x + h1v.y * w0v.y + h1v.z * w0v.z + h1v.w * w0v.w;
            acc11 += h1v.x * w1v.x + h1v.y * w1v.y + h1v.z * w1v.z + h1v.w * w1v.w;
        }

        float* hd = histb + (size_t)(t + 1) * NB * HD;
        hd[(size_t)na * HD + hc]           = tanhf(acc00);
        hd[(size_t)na * HD + hc + 1]       = tanhf(acc01);
        hd[(size_t)(na + 1) * HD + hc]     = tanhf(acc10);
        hd[(size_t)(na + 1) * HD + hc + 1] = tanhf(acc11);

        // -------- grid barrier (release h_t, acquire peers' h_t) --------
        __threadfence();
        __syncthreads();
        target += G;
        if (tid == 0) {
            atomicAdd(&g_bar, 1u);
            unsigned v;
            do {
                asm volatile("ld.acquire.gpu.u32 %0, [%1];"
                             : "=r"(v) : "l"(&g_bar));
            } while (v < target);
            __threadfence();
        }
        __syncthreads();
    }

    // Reset barrier for next graph replay (last CTA to exit does it)
    if (tid == 0) {
        unsigned v = atomicAdd(&g_bar_exit, 1u);
        if (v == G - 1) { g_bar_exit = 0u; g_bar = 0u; __threadfence(); }
    }
}

// h_out[d][n][h] = g_hist[d][1024][n][h]
__global__ void hcopy_kernel(float* __restrict__ out)
{
    int i = blockIdx.x * blockDim.x + threadIdx.x;  // over 16384 float4s
    if (i < (2 * NB * HD) / 4) {
        int d = i >> 13;          // 8192 float4 per direction
        int r = i & 8191;
        const float4* src =
            (const float4*)(g_hist + ((size_t)d * (LT + 1) + LT) * NB * HD) + r;
        float4* dst = (float4*)(out + (size_t)NB * LT * 2 * HD) + i;
        *dst = *src;
    }
}

// ---------------------------------------------------------------------------
extern "C" void kernel_launch(void* const* d_in, const int* in_sizes, int n_in,
                              void* d_out, int out_size)
{
    const float* x      = (const float*)d_in[0];
    const float* h0     = (const float*)d_in[1];
    const float* fw_Wih = (const float*)d_in[2];
    const float* fw_Whh = (const float*)d_in[3];
    const float* fw_bih = (const float*)d_in[4];
    const float* fw_bhh = (const float*)d_in[5];
    const float* fw_fcW = (const float*)d_in[6];
    const float* fw_fcb = (const float*)d_in[7];
    const float* bw_Wih = (const float*)d_in[8];
    const float* bw_Whh = (const float*)d_in[9];
    const float* bw_bih = (const float*)d_in[10];
    const float* bw_bhh = (const float*)d_in[11];
    const float* bw_fcW = (const float*)d_in[12];
    const float* bw_fcb = (const float*)d_in[13];
    float* y = (float*)d_out;

    const int rnn_smem = (64 + 8) * RSTR * 4;  // 148,608 bytes
    cudaFuncSetAttribute(rnn_kernel,
                         cudaFuncAttributeMaxDynamicSharedMemorySize, rnn_smem);

    dim3 gg(8, 1024);
    // Phase 1: x projection (+ both biases folded in), per direction
    gemm64<<<gg, 256>>>(x, fw_Wih, fw_bih, fw_bhh, nullptr, 0, 0);
    gemm64<<<gg, 256>>>(x, bw_Wih, bw_bih, bw_bhh, nullptr, 0, 1);
    // Phase 2: persistent recurrence over 1024 steps (both directions)
    rnn_kernel<<<128, 128, rnn_smem>>>(h0, fw_Whh, bw_Whh);
    // Phase 3: fc output projection + concat, per direction
    gemm64<<<gg, 256>>>(nullptr, fw_fcW, fw_fcb, nullptr, y, 1, 0);
    gemm64<<<gg, 256>>>(nullptr, bw_fcW, bw_fcb, nullptr, y, 1, 1);
    // Final hidden states
    hcopy_kernel<<<64, 256>>>(y);
}

// round 4
// speedup vs baseline: 1.3490x; 1.3490x over previous
#include <cuda_runtime.h>
#include <math.h>
#include <stdint.h>

#define NB 64
#define LT 1024
#define HD 512
#define RSTR 516   // padded smem row stride (floats): float4-aligned, 2-way worst conflict

// Scratch (static device arrays: allocation-free).
__device__ float g_pre[(size_t)2 * LT * NB * HD];
__device__ float g_hist[(size_t)2 * (LT + 1) * NB * HD];
__device__ unsigned g_arrive[128 * 32];   // per-CTA flag, 128B stride
__device__ unsigned g_bar_exit;

// ---------------------------------------------------------------------------
// Tiled fp32 GEMM: C[64x64 tile] = A(Mx512) * B(512x512 rows, K-major)^T
// mode 0: xproj  -> writes g_pre with time mapping (bw flips t), bias = b1+b2
// mode 1: fc     -> A = g_hist[dir][1..1024], writes y with dir column offset
// (measured at ~94% of FFMA peak; unchanged this round)
// ---------------------------------------------------------------------------
__global__ void __launch_bounds__(256) gemm64(
    const float* __restrict__ Ap, const float* __restrict__ B,
    const float* __restrict__ bias1, const float* __restrict__ bias2,
    float* __restrict__ yout, int mode, int dir)
{
    __shared__ float As[16][68];
    __shared__ float Bs[16][68];

    const float* A = (mode == 0)
        ? Ap
        : (g_hist + (size_t)dir * (LT + 1) * NB * HD + (size_t)NB * HD);

    const int m0 = blockIdx.y * 64;
    const int n0 = blockIdx.x * 64;
    const int tid  = threadIdx.x;
    const int lrow = tid >> 2;
    const int lk   = (tid & 3) << 2;
    const int tx = tid & 15;
    const int ty = tid >> 4;

    float acc[4][4];
#pragma unroll
    for (int i = 0; i < 4; i++)
#pragma unroll
        for (int j = 0; j < 4; j++) acc[i][j] = 0.f;

    for (int kt = 0; kt < HD; kt += 16) {
        float4 av = *(const float4*)(A + (size_t)(m0 + lrow) * HD + kt + lk);
        float4 bv = *(const float4*)(B + (size_t)(n0 + lrow) * HD + kt + lk);
        As[lk + 0][lrow] = av.x; As[lk + 1][lrow] = av.y;
        As[lk + 2][lrow] = av.z; As[lk + 3][lrow] = av.w;
        Bs[lk + 0][lrow] = bv.x; Bs[lk + 1][lrow] = bv.y;
        Bs[lk + 2][lrow] = bv.z; Bs[lk + 3][lrow] = bv.w;
        __syncthreads();
#pragma unroll
        for (int kk = 0; kk < 16; kk++) {
            float a[4], b[4];
            *(float4*)a = *(const float4*)&As[kk][ty << 2];
            *(float4*)b = *(const float4*)&Bs[kk][tx << 2];
#pragma unroll
            for (int i = 0; i < 4; i++)
#pragma unroll
                for (int j = 0; j < 4; j++) acc[i][j] += a[i] * b[j];
        }
        __syncthreads();
    }

    float bs[4];
#pragma unroll
    for (int j = 0; j < 4; j++) {
        int n = n0 + (tx << 2) + j;
        bs[j] = bias1[n] + (bias2 ? bias2[n] : 0.f);
    }

#pragma unroll
    for (int i = 0; i < 4; i++) {
        int m = m0 + (ty << 2) + i;
#pragma unroll
        for (int j = 0; j < 4; j++) {
            int n = n0 + (tx << 2) + j;
            float v = acc[i][j] + bs[j];
            if (mode == 0) {
                int nb = m >> 10, tt = m & (LT - 1);
                int td = dir ? (LT - 1 - tt) : tt;
                g_pre[(((size_t)dir * LT + td) * NB + nb) * HD + n] = v;
            } else {
                int t = m >> 6, nb = m & (NB - 1);
                yout[((size_t)nb * LT + t) * (2 * HD) + (size_t)dir * HD + n] = v;
            }
        }
    }
}

// ---------------------------------------------------------------------------
// Persistent recurrence: 128 CTAs x 256 threads. K split in half across the
// two thread-halves (2 warps/SMSP to hide latency); flag-based grid barrier
// (no atomics on the hot path); pre[t] prefetched ahead of the FMA loop.
// CTA = (dir, 64-wide h block, 8-wide n block); Whh slice resident in SMEM.
// ---------------------------------------------------------------------------
__global__ void __launch_bounds__(256) rnn_kernel(
    const float* __restrict__ h0in,
    const float* __restrict__ Wfw, const float* __restrict__ Wbw)
{
    extern __shared__ float sm[];
    float* Wsh = sm;                     // 64 rows x RSTR
    float* hsh = sm + 64 * RSTR;         // 8 rows  x RSTR
    float* xch = sm + (64 + 8) * RSTR;   // 128 x 4 partial exchange

    const int b   = blockIdx.x;
    const int dir = b >> 6;
    const int sub = b & 63;
    const int hb  = (sub >> 3) << 6;     // h block base (0..448)
    const int nb  = (sub & 7) << 3;      // n block base (0..56)
    const int tid = threadIdx.x;
    const float* W = dir ? Wbw : Wfw;

    // Load Whh slice [64][512] once (resident for all 1024 steps)
    for (int i = tid; i < 64 * 128; i += 256) {
        int r = i >> 7, c4 = (i & 127) << 2;
        *(float4*)&Wsh[r * RSTR + c4] =
            *(const float4*)&W[(size_t)(hb + r) * HD + c4];
    }

    const float* preb  = g_pre  + (size_t)dir * LT * NB * HD;
    float*       histb = g_hist + (size_t)dir * (LT + 1) * NB * HD;

    const int khalf = tid >> 7;          // 0 or 1: K half
    const int lid   = tid & 127;
    const int a     = lid & 3;           // n-pair (4 -> 8 rows)
    const int c     = lid >> 2;          // h-pair (32 -> 64 cols)
    const int na = nb + (a << 1);
    const int hc = hb + (c << 1);
    const int k0 = khalf << 8;           // 0 or 256
    const float* hr0 = &hsh[(a << 1) * RSTR + k0];
    const float* hr1 = hr0 + RSTR;
    const float* wr0 = &Wsh[(c << 1) * RSTR + k0];
    const float* wr1 = wr0 + RSTR;

    __syncthreads();

    for (int t = 0; t < LT; t++) {
        // ---- wait for h_{t-1} (flags from all 128 CTAs reach t) ----
        if (tid < 128) {
            const unsigned* flag = &g_arrive[tid * 32];
            unsigned v;
            do {
                asm volatile("ld.acquire.gpu.u32 %0, [%1];" : "=r"(v) : "l"(flag));
            } while (v < (unsigned)t);
        }
        __syncthreads();

        // ---- stage h_{t-1} rows nb..nb+7 (16 KB) into SMEM ----
        const float* hsrc = (t == 0)
            ? (h0in + ((size_t)dir * NB + nb) * HD)
            : (histb + ((size_t)t * NB + nb) * HD);
        for (int i = tid; i < 8 * 128; i += 256) {
            int r = i >> 7, c4 = (i & 127) << 2;
            *(float4*)&hsh[r * RSTR + c4] =
                *(const float4*)&hsrc[(size_t)r * HD + c4];
        }
        __syncthreads();

        // ---- prefetch pre[t] for this thread's outputs (reducers only) ----
        float2 p0, p1;
        if (khalf == 0) {
            const float* pr = preb + (size_t)t * NB * HD;
            p0 = *(const float2*)(pr + (size_t)na * HD + hc);
            p1 = *(const float2*)(pr + (size_t)(na + 1) * HD + hc);
        }

        // ---- half-K GEMM: 2x2 tile, 256 K-iters per thread-half ----
        float acc00 = 0.f, acc01 = 0.f, acc10 = 0.f, acc11 = 0.f;
#pragma unroll 4
        for (int k = 0; k < 256; k += 4) {
            float4 h0v = *(const float4*)(hr0 + k);
            float4 h1v = *(const float4*)(hr1 + k);
            float4 w0v = *(const float4*)(wr0 + k);
            float4 w1v = *(const float4*)(wr1 + k);
            acc00 += h0v.x * w0v.x + h0v.y * w0v.y + h0v.z * w0v.z + h0v.w * w0v.w;
            acc01 += h0v.x * w1v.x + h0v.y * w1v.y + h0v.z * w1v.z + h0v.w * w1v.w;
            acc10 += h1v.x * w0v.x + h1v.y * w0v.y + h1v.z * w0v.z + h1v.w * w0v.w;
            acc11 += h1v.x * w1v.x + h1v.y * w1v.y + h1v.z * w1v.z + h1v.w * w1v.w;
        }

        // ---- cross-half reduction via SMEM, then tanh + store ----
        if (khalf) {
            *(float4*)&xch[lid << 2] = make_float4(acc00, acc01, acc10, acc11);
        }
        __syncthreads();
        if (khalf == 0) {
            float4 px = *(const float4*)&xch[lid << 2];
            float* hd = histb + (size_t)(t + 1) * NB * HD;
            float2 o0, o1;
            o0.x = tanhf(acc00 + px.x + p0.x);
            o0.y = tanhf(acc01 + px.y + p0.y);
            o1.x = tanhf(acc10 + px.z + p1.x);
            o1.y = tanhf(acc11 + px.w + p1.y);
            *(float2*)(hd + (size_t)na * HD + hc)       = o0;
            *(float2*)(hd + (size_t)(na + 1) * HD + hc) = o1;
        }
        __syncthreads();

        // ---- publish: this CTA's slice of h_t is globally visible ----
        if (tid == 0) {
            __threadfence();
            asm volatile("st.release.gpu.u32 [%0], %1;"
                         :: "l"(&g_arrive[b * 32]), "r"((unsigned)(t + 1)) : "memory");
        }
    }

    // Reset flags for the next graph replay (last CTA to exit does it)
    __syncthreads();
    if (tid == 0) {
        unsigned v = atomicAdd(&g_bar_exit, 1u);
        if (v == 127u) {
            for (int i = 0; i < 128; i++) g_arrive[i * 32] = 0u;
            g_bar_exit = 0u;
            __threadfence();
        }
    }
}

// h_out[d][n][h] = g_hist[d][1024][n][h]
__global__ void hcopy_kernel(float* __restrict__ out)
{
    int i = blockIdx.x * blockDim.x + threadIdx.x;
    if (i < (2 * NB * HD) / 4) {
        int d = i >> 13;
        int r = i & 8191;
        const float4* src =
            (const float4*)(g_hist + ((size_t)d * (LT + 1) + LT) * NB * HD) + r;
        float4* dst = (float4*)(out + (size_t)NB * LT * 2 * HD) + i;
        *dst = *src;
    }
}

// ---------------------------------------------------------------------------
extern "C" void kernel_launch(void* const* d_in, const int* in_sizes, int n_in,
                              void* d_out, int out_size)
{
    const float* x      = (const float*)d_in[0];
    const float* h0     = (const float*)d_in[1];
    const float* fw_Wih = (const float*)d_in[2];
    const float* fw_Whh = (const float*)d_in[3];
    const float* fw_bih = (const float*)d_in[4];
    const float* fw_bhh = (const float*)d_in[5];
    const float* fw_fcW = (const float*)d_in[6];
    const float* fw_fcb = (const float*)d_in[7];
    const float* bw_Wih = (const float*)d_in[8];
    const float* bw_Whh = (const float*)d_in[9];
    const float* bw_bih = (const float*)d_in[10];
    const float* bw_bhh = (const float*)d_in[11];
    const float* bw_fcW = (const float*)d_in[12];
    const float* bw_fcb = (const float*)d_in[13];
    float* y = (float*)d_out;

    const int rnn_smem = (64 + 8) * RSTR * 4 + 128 * 4 * 4;  // 150,656 B
    cudaFuncSetAttribute(rnn_kernel,
                         cudaFuncAttributeMaxDynamicSharedMemorySize, rnn_smem);

    dim3 gg(8, 1024);
    // Phase 1: x projection (+ both biases folded in), per direction
    gemm64<<<gg, 256>>>(x, fw_Wih, fw_bih, fw_bhh, nullptr, 0, 0);
    gemm64<<<gg, 256>>>(x, bw_Wih, bw_bih, bw_bhh, nullptr, 0, 1);
    // Phase 2: persistent recurrence over 1024 steps (both directions)
    rnn_kernel<<<128, 256, rnn_smem>>>(h0, fw_Whh, bw_Whh);
    // Phase 3: fc output projection + concat, per direction
    gemm64<<<gg, 256>>>(nullptr, fw_fcW, fw_fcb, nullptr, y, 1, 0);
    gemm64<<<gg, 256>>>(nullptr, bw_fcW, bw_fcb, nullptr, y, 1, 1);
    // Final hidden states
    hcopy_kernel<<<64, 256>>>(y);
}